// round 10
// baseline (speedup 1.0000x reference)
#include <cuda_runtime.h>
#include <cuda_bf16.h>
#include <cstdint>

// Sparsemax along last dim of a [ROWS, 32000] fp32 matrix.
//
// Exact, sort-free: tau solves sum_i max(x_i - tau, 0) = 1 and tau >= rowmax-1,
// so the support lies in C = {x > rowmax - 1} (~25 elems/row, Gaussian data).
//
// Persistent CTAs (grid = #SMs, 1024 threads). Row split:
//   - 96 KB (24576 floats) via TMA -> SMEM, single buffer, R6 protocol:
//     issued at barrier A, delivered during the compute phase (never under
//     the LDS copy — proven crossbar poison in R4/R7/R9).
//   - 29 KB tail (7424 floats) via direct LDG -> registers, issued right
//     after the mbar wait so its DRAM reads run DURING the copy window,
//     filling the only DRAM-idle gap of the R6 schedule.
// Two block barriers per row; all warps redundantly run Michelot on the
// compacted candidate list (no broadcast barrier). Evict-first stores.

#define SMX_N        32000
#define SMX_N4       8000
#define SMX_SM_F4    6144           // float4 in SMEM part (6/thread exactly)
#define SMX_SM_FL    24576
#define SMX_SM_B     98304
#define SMX_T1_F4    1024           // tail part 1: full (idx 6144+t)
#define SMX_T2_F4    832            // tail part 2: t < 832 (idx 7168+t)
#define SMX_THREADS  1024
#define SMX_NEG      (-3.0e38f)
#define SMX_CAP      1024

__device__ __forceinline__ uint32_t smx_smem_u32(const void* p) {
    uint32_t a;
    asm("{ .reg .u64 t; cvta.to.shared.u64 t, %1; cvt.u32.u64 %0, t; }"
        : "=r"(a) : "l"(p));
    return a;
}
__device__ __forceinline__ void smx_mbar_init(uint32_t mbar, uint32_t count) {
    asm volatile("mbarrier.init.shared.b64 [%0], %1;" :: "r"(mbar), "r"(count) : "memory");
}
__device__ __forceinline__ void smx_expect_tx(uint32_t mbar, uint32_t bytes) {
    asm volatile("mbarrier.arrive.expect_tx.shared.b64 _, [%0], %1;"
                 :: "r"(mbar), "r"(bytes) : "memory");
}
__device__ __forceinline__ void smx_bulk_g2s(uint32_t dst, const void* src,
                                             uint32_t bytes, uint32_t mbar) {
    asm volatile(
        "cp.async.bulk.shared::cta.global.mbarrier::complete_tx::bytes [%0], [%1], %2, [%3];"
        :: "r"(dst), "l"(src), "r"(bytes), "r"(mbar) : "memory");
}
__device__ __forceinline__ void smx_mbar_wait(uint32_t mbar, uint32_t parity) {
    asm volatile(
        "{\n\t"
        ".reg .pred P;\n\t"
        "SMXW%=:\n\t"
        "mbarrier.try_wait.parity.acquire.cta.shared::cta.b64 P, [%0], %1, 0x989680;\n\t"
        "@P bra SMXD%=;\n\t"
        "bra SMXW%=;\n\t"
        "SMXD%=:\n\t"
        "}"
        :: "r"(mbar), "r"(parity) : "memory");
}
__device__ __forceinline__ void smx_fence_async() {
    asm volatile("fence.proxy.async.shared::cta;" ::: "memory");
}

// order-preserving float<->uint for shared atomicMax
__device__ __forceinline__ unsigned smx_enc(float f) {
    unsigned b = __float_as_uint(f);
    return (b & 0x80000000u) ? ~b : (b | 0x80000000u);
}
__device__ __forceinline__ float smx_dec(unsigned u) {
    return (u & 0x80000000u) ? __uint_as_float(u & 0x7fffffffu)
                             : __uint_as_float(~u);
}

extern __shared__ float smx_buf[];   // 24576 floats = 96 KB

__global__ __launch_bounds__(SMX_THREADS, 1)
void sparsemax_kernel(const float* __restrict__ x, float* __restrict__ y, int rows) {
    const int t    = threadIdx.x;
    const int lane = t & 31;
    const int stride = gridDim.x;

    __shared__ __align__(8) uint64_t s_mbar;
    __shared__ unsigned s_maxbits[2];
    __shared__ int      s_cnt[2];
    __shared__ float    s_red[2][2];          // fallback accumulators
    __shared__ float    s_cand[2][SMX_CAP];

    const uint32_t mbar = smx_smem_u32(&s_mbar);
    const uint32_t sbuf = smx_smem_u32(smx_buf);

    if (t == 0) {
        smx_mbar_init(mbar, 1);
        s_maxbits[0] = 0u;  s_cnt[0] = 0;
        s_maxbits[1] = 0u;  s_cnt[1] = 0;
    }
    __syncthreads();

    const int row0 = blockIdx.x;
    if (row0 >= rows) return;

    if (t == 0) {
        smx_expect_tx(mbar, SMX_SM_B);
        smx_bulk_g2s(sbuf, x + (size_t)row0 * SMX_N, SMX_SM_B, mbar);
    }

    uint32_t parity = 0;   // mbarrier phase
    unsigned p = 0;        // row-parity for scratch slots

    for (int r = row0; r < rows; r += stride) {
        smx_mbar_wait(mbar, parity);
        parity ^= 1u;

        const float4* __restrict__ xr4 =
            reinterpret_cast<const float4*>(x + (size_t)r * SMX_N);

        // ---- tail LDGs issued FIRST: their DRAM reads run during the copy ----
        float4 v[8];
        v[6] = __ldg(&xr4[SMX_SM_F4 + t]);                     // [6144,7168)
        if (t < SMX_T2_F4) v[7] = __ldg(&xr4[SMX_SM_F4 + SMX_T1_F4 + t]);  // [7168,8000)
        else               v[7] = make_float4(SMX_NEG, SMX_NEG, SMX_NEG, SMX_NEG);

        // ---- SMEM -> registers with fused running max ----
        float m = SMX_NEG;
        {
            const float4* s4 = reinterpret_cast<const float4*>(smx_buf);
            #pragma unroll
            for (int i = 0; i < 6; i++) {                      // no bounds checks
                v[i] = s4[i * SMX_THREADS + t];
                m = fmaxf(m, fmaxf(fmaxf(v[i].x, v[i].y), fmaxf(v[i].z, v[i].w)));
            }
        }
        // fold in the LDG tail (loads have drained under the LDS copy)
        m = fmaxf(m, fmaxf(fmaxf(v[6].x, v[6].y), fmaxf(v[6].z, v[6].w)));
        m = fmaxf(m, fmaxf(fmaxf(v[7].x, v[7].y), fmaxf(v[7].z, v[7].w)));

        // warp max-reduce + shared atomicMax (pre-barrier)
        #pragma unroll
        for (int o = 16; o; o >>= 1)
            m = fmaxf(m, __shfl_xor_sync(0xffffffffu, m, o));
        if (lane == 0) atomicMax(&s_maxbits[p], smx_enc(m));

        __syncthreads();   // barrier A: buffer reads done + rowmax published

        // t0: release buffer to the async proxy, issue next row's SMEM part
        if (t == 0 && r + stride < rows) {
            smx_fence_async();
            smx_expect_tx(mbar, SMX_SM_B);
            smx_bulk_g2s(sbuf, x + (size_t)(r + stride) * SMX_N, SMX_SM_B, mbar);
        }

        const float thr = smx_dec(s_maxbits[p]) - 1.0f;   // tau >= thr always
        if (t == 1) { s_maxbits[p ^ 1] = 0u; s_cnt[p ^ 1] = 0; }  // prep next slot

        // ---- compact candidates {x > thr} into s_cand[p] ----
        #pragma unroll
        for (int i = 0; i < 8; i++) {
            const float a0 = v[i].x, a1 = v[i].y, a2 = v[i].z, a3 = v[i].w;
            if (a0 > thr) { int k = atomicAdd(&s_cnt[p], 1); if (k < SMX_CAP) s_cand[p][k] = a0; }
            if (a1 > thr) { int k = atomicAdd(&s_cnt[p], 1); if (k < SMX_CAP) s_cand[p][k] = a1; }
            if (a2 > thr) { int k = atomicAdd(&s_cnt[p], 1); if (k < SMX_CAP) s_cand[p][k] = a2; }
            if (a3 > thr) { int k = atomicAdd(&s_cnt[p], 1); if (k < SMX_CAP) s_cand[p][k] = a3; }
        }
        __syncthreads();   // barrier B: candidate list complete
        const int cnt = s_cnt[p];

        float tau;
        if (cnt <= SMX_CAP) {
            // ---- every warp redundantly: Michelot on the candidate list ----
            tau = thr;
            float prevc = -1.0f;
            #pragma unroll 1
            for (int it = 0; it < 64; it++) {
                float s = 0.0f, c = 0.0f;
                for (int j = lane; j < cnt; j += 32) {
                    const float z = s_cand[p][j];
                    if (z > tau) { s += z; c += 1.0f; }
                }
                #pragma unroll
                for (int o = 16; o; o >>= 1) {
                    s += __shfl_xor_sync(0xffffffffu, s, o);
                    c += __shfl_xor_sync(0xffffffffu, c, o);
                }
                tau = (s - 1.0f) / c;
                if (c == prevc) break;        // fixed point: exact tau
                prevc = c;
            }
        } else {
            // ---- fallback: full-row Michelot via shared atomics (rare) ----
            if (t == 0) { s_red[0][0] = 0.f; s_red[0][1] = 0.f;
                          s_red[1][0] = 0.f; s_red[1][1] = 0.f; }
            __syncthreads();
            tau = thr;
            float prevc = -1.0f;
            unsigned q = 0;
            #pragma unroll 1
            for (int it = 0; it < 64; it++) {
                float s = 0.0f, c = 0.0f;
                #pragma unroll
                for (int i = 0; i < 8; i++) {
                    if (v[i].x > tau) { s += v[i].x; c += 1.0f; }
                    if (v[i].y > tau) { s += v[i].y; c += 1.0f; }
                    if (v[i].z > tau) { s += v[i].z; c += 1.0f; }
                    if (v[i].w > tau) { s += v[i].w; c += 1.0f; }
                }
                #pragma unroll
                for (int o = 16; o; o >>= 1) {
                    s += __shfl_xor_sync(0xffffffffu, s, o);
                    c += __shfl_xor_sync(0xffffffffu, c, o);
                }
                if (lane == 0) { atomicAdd(&s_red[q][0], s); atomicAdd(&s_red[q][1], c); }
                if (t == 0)    { s_red[q ^ 1][0] = 0.f; s_red[q ^ 1][1] = 0.f; }
                __syncthreads();
                const float S = s_red[q][0], C = s_red[q][1];
                __syncthreads();
                tau = (S - 1.0f) / C;
                if (C == prevc) break;
                prevc = C;
                q ^= 1;
            }
        }

        // ---- output: max(x - tau, 0), coalesced, evict-first ----
        float4* __restrict__ yr = reinterpret_cast<float4*>(y + (size_t)r * SMX_N);
        #pragma unroll
        for (int i = 0; i < 6; i++) {
            float4 o;
            o.x = fmaxf(v[i].x - tau, 0.0f);
            o.y = fmaxf(v[i].y - tau, 0.0f);
            o.z = fmaxf(v[i].z - tau, 0.0f);
            o.w = fmaxf(v[i].w - tau, 0.0f);
            __stcs(&yr[i * SMX_THREADS + t], o);
        }
        {
            float4 o;
            o.x = fmaxf(v[6].x - tau, 0.0f);
            o.y = fmaxf(v[6].y - tau, 0.0f);
            o.z = fmaxf(v[6].z - tau, 0.0f);
            o.w = fmaxf(v[6].w - tau, 0.0f);
            __stcs(&yr[SMX_SM_F4 + t], o);
        }
        if (t < SMX_T2_F4) {
            float4 o;
            o.x = fmaxf(v[7].x - tau, 0.0f);
            o.y = fmaxf(v[7].y - tau, 0.0f);
            o.z = fmaxf(v[7].z - tau, 0.0f);
            o.w = fmaxf(v[7].w - tau, 0.0f);
            __stcs(&yr[SMX_SM_F4 + SMX_T1_F4 + t], o);
        }

        p ^= 1u;
    }
}

extern "C" void kernel_launch(void* const* d_in, const int* in_sizes, int n_in,
                              void* d_out, int out_size) {
    const float* x = (const float*)d_in[0];
    float* y = (float*)d_out;
    const int rows = in_sizes[0] / SMX_N;

    int dev = 0, sms = 148;
    cudaGetDevice(&dev);
    cudaDeviceGetAttribute(&sms, cudaDevAttrMultiProcessorCount, dev);

    static bool attr_done = false;
    if (!attr_done) {
        cudaFuncSetAttribute(sparsemax_kernel,
                             cudaFuncAttributeMaxDynamicSharedMemorySize,
                             SMX_SM_B);
        attr_done = true;
    }

    int grid = rows < sms ? rows : sms;
    sparsemax_kernel<<<grid, SMX_THREADS, SMX_SM_B>>>(x, y, rows);
}

// round 11
// speedup vs baseline: 1.1404x; 1.1404x over previous
#include <cuda_runtime.h>
#include <cuda_bf16.h>
#include <cstdint>

// Sparsemax along last dim of a [ROWS, 32000] fp32 matrix.
//
// Exact, sort-free: tau solves sum_i max(x_i - tau, 0) = 1 and tau >= rowmax-1,
// so the support lies in C = {x > rowmax - 1} (~25 elems/row, Gaussian data).
//
// Persistent CTAs (grid = #SMs, 1024 threads). Whole row TMA'd into a single
// 128 KB SMEM buffer one row ahead; row register-resident (8 x float4/thread).
// Schedule (empirical optimum over 10 rounds): the next-row TMA is issued at
// barrier A and delivers ONLY during the compute phase — never concurrent
// with the LDS copy (crossbar contention, proven regressions R4/R7/R9/R10).
// Two block barriers per row; all warps redundantly run Michelot on the
// compacted candidate list (no broadcast barrier). Evict-first stores.

#define SMX_N        32000
#define SMX_N4       8000
#define SMX_ROWBYTES 128000
#define SMX_THREADS  1024
#define SMX_LAST_F4  832            // i=7 slice: idx 7168 + t, valid for t < 832
#define SMX_NEG      (-3.0e38f)
#define SMX_CAP      1024

__device__ __forceinline__ uint32_t smx_smem_u32(const void* p) {
    uint32_t a;
    asm("{ .reg .u64 t; cvta.to.shared.u64 t, %1; cvt.u32.u64 %0, t; }"
        : "=r"(a) : "l"(p));
    return a;
}
__device__ __forceinline__ void smx_mbar_init(uint32_t mbar, uint32_t count) {
    asm volatile("mbarrier.init.shared.b64 [%0], %1;" :: "r"(mbar), "r"(count) : "memory");
}
__device__ __forceinline__ void smx_expect_tx(uint32_t mbar, uint32_t bytes) {
    asm volatile("mbarrier.arrive.expect_tx.shared.b64 _, [%0], %1;"
                 :: "r"(mbar), "r"(bytes) : "memory");
}
__device__ __forceinline__ void smx_bulk_g2s(uint32_t dst, const void* src,
                                             uint32_t bytes, uint32_t mbar) {
    asm volatile(
        "cp.async.bulk.shared::cta.global.mbarrier::complete_tx::bytes [%0], [%1], %2, [%3];"
        :: "r"(dst), "l"(src), "r"(bytes), "r"(mbar) : "memory");
}
__device__ __forceinline__ void smx_mbar_wait(uint32_t mbar, uint32_t parity) {
    asm volatile(
        "{\n\t"
        ".reg .pred P;\n\t"
        "SMXW%=:\n\t"
        "mbarrier.try_wait.parity.acquire.cta.shared::cta.b64 P, [%0], %1, 0x989680;\n\t"
        "@P bra SMXD%=;\n\t"
        "bra SMXW%=;\n\t"
        "SMXD%=:\n\t"
        "}"
        :: "r"(mbar), "r"(parity) : "memory");
}
__device__ __forceinline__ void smx_fence_async() {
    asm volatile("fence.proxy.async.shared::cta;" ::: "memory");
}

// order-preserving float<->uint for shared atomicMax
__device__ __forceinline__ unsigned smx_enc(float f) {
    unsigned b = __float_as_uint(f);
    return (b & 0x80000000u) ? ~b : (b | 0x80000000u);
}
__device__ __forceinline__ float smx_dec(unsigned u) {
    return (u & 0x80000000u) ? __uint_as_float(u & 0x7fffffffu)
                             : __uint_as_float(~u);
}

extern __shared__ float smx_buf[];   // 32000 floats = 128 KB

__global__ __launch_bounds__(SMX_THREADS, 1)
void sparsemax_kernel(const float* __restrict__ x, float* __restrict__ y, int rows) {
    const int t    = threadIdx.x;
    const int lane = t & 31;
    const int stride = gridDim.x;

    __shared__ __align__(8) uint64_t s_mbar;
    __shared__ unsigned s_maxbits[2];
    __shared__ int      s_cnt[2];
    __shared__ float    s_red[2][2];          // fallback accumulators
    __shared__ float    s_cand[2][SMX_CAP];

    const uint32_t mbar = smx_smem_u32(&s_mbar);
    const uint32_t sbuf = smx_smem_u32(smx_buf);

    if (t == 0) {
        smx_mbar_init(mbar, 1);
        s_maxbits[0] = 0u;  s_cnt[0] = 0;
        s_maxbits[1] = 0u;  s_cnt[1] = 0;
    }
    __syncthreads();

    const int row0 = blockIdx.x;
    if (row0 >= rows) return;

    if (t == 0) {
        smx_expect_tx(mbar, SMX_ROWBYTES);
        smx_bulk_g2s(sbuf, x + (size_t)row0 * SMX_N, SMX_ROWBYTES, mbar);
    }

    uint32_t parity = 0;   // mbarrier phase
    unsigned p = 0;        // row-parity for scratch slots

    for (int r = row0; r < rows; r += stride) {
        smx_mbar_wait(mbar, parity);
        parity ^= 1u;

        // ---- SMEM -> registers with fused running max ----
        // i = 0..6 are always in-bounds (7*1024+1023 = 8191 -> idx < 7168+t,
        // max 8191? no: i<7 gives idx <= 6*1024+1023 = 7167 < 8000). Only the
        // i=7 slice needs the t < 832 check.
        float4 v[8];
        float m = SMX_NEG;
        const float4* s4 = reinterpret_cast<const float4*>(smx_buf);
        #pragma unroll
        for (int i = 0; i < 7; i++) {
            v[i] = s4[i * SMX_THREADS + t];
            m = fmaxf(m, fmaxf(fmaxf(v[i].x, v[i].y), fmaxf(v[i].z, v[i].w)));
        }
        if (t < SMX_LAST_F4) {
            v[7] = s4[7 * SMX_THREADS + t];
            m = fmaxf(m, fmaxf(fmaxf(v[7].x, v[7].y), fmaxf(v[7].z, v[7].w)));
        } else {
            v[7] = make_float4(SMX_NEG, SMX_NEG, SMX_NEG, SMX_NEG);
        }

        // warp max-reduce + shared atomicMax (pre-barrier)
        #pragma unroll
        for (int o = 16; o; o >>= 1)
            m = fmaxf(m, __shfl_xor_sync(0xffffffffu, m, o));
        if (lane == 0) atomicMax(&s_maxbits[p], smx_enc(m));

        __syncthreads();   // barrier A: buffer reads done + rowmax published

        // t0: release buffer to the async proxy, prefetch next row
        if (t == 0 && r + stride < rows) {
            smx_fence_async();
            smx_expect_tx(mbar, SMX_ROWBYTES);
            smx_bulk_g2s(sbuf, x + (size_t)(r + stride) * SMX_N, SMX_ROWBYTES, mbar);
        }

        const float thr = smx_dec(s_maxbits[p]) - 1.0f;   // tau >= thr always
        if (t == 1) { s_maxbits[p ^ 1] = 0u; s_cnt[p ^ 1] = 0; }  // prep next slot

        // ---- compact candidates {x > thr} into s_cand[p] ----
        int*   cntp  = &s_cnt[p];
        float* candp = s_cand[p];
        #pragma unroll
        for (int i = 0; i < 8; i++) {
            const float a0 = v[i].x, a1 = v[i].y, a2 = v[i].z, a3 = v[i].w;
            if (a0 > thr) { int k = atomicAdd(cntp, 1); if (k < SMX_CAP) candp[k] = a0; }
            if (a1 > thr) { int k = atomicAdd(cntp, 1); if (k < SMX_CAP) candp[k] = a1; }
            if (a2 > thr) { int k = atomicAdd(cntp, 1); if (k < SMX_CAP) candp[k] = a2; }
            if (a3 > thr) { int k = atomicAdd(cntp, 1); if (k < SMX_CAP) candp[k] = a3; }
        }
        __syncthreads();   // barrier B: candidate list complete
        const int cnt = *cntp;

        float tau;
        if (cnt <= SMX_CAP) {
            // ---- every warp redundantly: Michelot on the candidate list ----
            tau = thr;
            float prevc = -1.0f;
            #pragma unroll 1
            for (int it = 0; it < 64; it++) {
                float s = 0.0f, c = 0.0f;
                for (int j = lane; j < cnt; j += 32) {
                    const float z = candp[j];
                    if (z > tau) { s += z; c += 1.0f; }
                }
                #pragma unroll
                for (int o = 16; o; o >>= 1) {
                    s += __shfl_xor_sync(0xffffffffu, s, o);
                    c += __shfl_xor_sync(0xffffffffu, c, o);
                }
                tau = (s - 1.0f) / c;
                if (c == prevc) break;        // fixed point: exact tau
                prevc = c;
            }
        } else {
            // ---- fallback: full-row Michelot via shared atomics (rare) ----
            if (t == 0) { s_red[0][0] = 0.f; s_red[0][1] = 0.f;
                          s_red[1][0] = 0.f; s_red[1][1] = 0.f; }
            __syncthreads();
            tau = thr;
            float prevc = -1.0f;
            unsigned q = 0;
            #pragma unroll 1
            for (int it = 0; it < 64; it++) {
                float s = 0.0f, c = 0.0f;
                #pragma unroll
                for (int i = 0; i < 8; i++) {
                    if (v[i].x > tau) { s += v[i].x; c += 1.0f; }
                    if (v[i].y > tau) { s += v[i].y; c += 1.0f; }
                    if (v[i].z > tau) { s += v[i].z; c += 1.0f; }
                    if (v[i].w > tau) { s += v[i].w; c += 1.0f; }
                }
                #pragma unroll
                for (int o = 16; o; o >>= 1) {
                    s += __shfl_xor_sync(0xffffffffu, s, o);
                    c += __shfl_xor_sync(0xffffffffu, c, o);
                }
                if (lane == 0) { atomicAdd(&s_red[q][0], s); atomicAdd(&s_red[q][1], c); }
                if (t == 0)    { s_red[q ^ 1][0] = 0.f; s_red[q ^ 1][1] = 0.f; }
                __syncthreads();
                const float S = s_red[q][0], C = s_red[q][1];
                __syncthreads();
                tau = (S - 1.0f) / C;
                if (C == prevc) break;
                prevc = C;
                q ^= 1;
            }
        }

        // ---- output: max(x - tau, 0), coalesced, evict-first ----
        float4* __restrict__ yr = reinterpret_cast<float4*>(y + (size_t)r * SMX_N);
        #pragma unroll
        for (int i = 0; i < 7; i++) {
            float4 o;
            o.x = fmaxf(v[i].x - tau, 0.0f);
            o.y = fmaxf(v[i].y - tau, 0.0f);
            o.z = fmaxf(v[i].z - tau, 0.0f);
            o.w = fmaxf(v[i].w - tau, 0.0f);
            __stcs(&yr[i * SMX_THREADS + t], o);
        }
        if (t < SMX_LAST_F4) {
            float4 o;
            o.x = fmaxf(v[7].x - tau, 0.0f);
            o.y = fmaxf(v[7].y - tau, 0.0f);
            o.z = fmaxf(v[7].z - tau, 0.0f);
            o.w = fmaxf(v[7].w - tau, 0.0f);
            __stcs(&yr[7 * SMX_THREADS + t], o);
        }

        p ^= 1u;
    }
}

extern "C" void kernel_launch(void* const* d_in, const int* in_sizes, int n_in,
                              void* d_out, int out_size) {
    const float* x = (const float*)d_in[0];
    float* y = (float*)d_out;
    const int rows = in_sizes[0] / SMX_N;

    int dev = 0, sms = 148;
    cudaGetDevice(&dev);
    cudaDeviceGetAttribute(&sms, cudaDevAttrMultiProcessorCount, dev);

    static bool attr_done = false;
    if (!attr_done) {
        cudaFuncSetAttribute(sparsemax_kernel,
                             cudaFuncAttributeMaxDynamicSharedMemorySize,
                             SMX_ROWBYTES);
        attr_done = true;
    }

    int grid = rows < sms ? rows : sms;
    sparsemax_kernel<<<grid, SMX_THREADS, SMX_ROWBYTES>>>(x, y, rows);
}

// round 12
// speedup vs baseline: 1.1603x; 1.0174x over previous
#include <cuda_runtime.h>
#include <cuda_bf16.h>
#include <cstdint>

// Sparsemax along last dim of a [ROWS, 32000] fp32 matrix.
//
// Exact, sort-free: tau solves sum_i max(x_i - tau, 0) = 1 and tau >= rowmax-1,
// so the support lies in C = {x > rowmax - 1} (~25 elems/row, Gaussian data).
//
// Persistent CTAs (grid = #SMs, 1024 threads). Whole row TMA'd into a single
// 128 KB SMEM buffer one row ahead; row register-resident (8 x float4/thread).
// Schedule (empirical optimum over 11 rounds): the next-row TMA is issued at
// barrier A and delivers ONLY during the compute phase — never concurrent
// with the LDS copy (crossbar contention, proven regressions R4/R7/R9/R10).
//
// R12: the pre-barrier-A critical path is trimmed — each warp publishes its
// max with a plain STS (no shared atomicMax serialization); the 32->1 combine
// is done redundantly by every thread AFTER barrier A, off the TMA-issue path.
// Two block barriers per row; all warps redundantly run Michelot on the
// compacted candidate list (no broadcast barrier). Evict-first stores.

#define SMX_N        32000
#define SMX_N4       8000
#define SMX_ROWBYTES 128000
#define SMX_THREADS  1024
#define SMX_LAST_F4  832            // i=7 slice: idx 7168 + t, valid for t < 832
#define SMX_NEG      (-3.0e38f)
#define SMX_CAP      1024

__device__ __forceinline__ uint32_t smx_smem_u32(const void* p) {
    uint32_t a;
    asm("{ .reg .u64 t; cvta.to.shared.u64 t, %1; cvt.u32.u64 %0, t; }"
        : "=r"(a) : "l"(p));
    return a;
}
__device__ __forceinline__ void smx_mbar_init(uint32_t mbar, uint32_t count) {
    asm volatile("mbarrier.init.shared.b64 [%0], %1;" :: "r"(mbar), "r"(count) : "memory");
}
__device__ __forceinline__ void smx_expect_tx(uint32_t mbar, uint32_t bytes) {
    asm volatile("mbarrier.arrive.expect_tx.shared.b64 _, [%0], %1;"
                 :: "r"(mbar), "r"(bytes) : "memory");
}
__device__ __forceinline__ void smx_bulk_g2s(uint32_t dst, const void* src,
                                             uint32_t bytes, uint32_t mbar) {
    asm volatile(
        "cp.async.bulk.shared::cta.global.mbarrier::complete_tx::bytes [%0], [%1], %2, [%3];"
        :: "r"(dst), "l"(src), "r"(bytes), "r"(mbar) : "memory");
}
__device__ __forceinline__ void smx_mbar_wait(uint32_t mbar, uint32_t parity) {
    asm volatile(
        "{\n\t"
        ".reg .pred P;\n\t"
        "SMXW%=:\n\t"
        "mbarrier.try_wait.parity.acquire.cta.shared::cta.b64 P, [%0], %1, 0x989680;\n\t"
        "@P bra SMXD%=;\n\t"
        "bra SMXW%=;\n\t"
        "SMXD%=:\n\t"
        "}"
        :: "r"(mbar), "r"(parity) : "memory");
}
__device__ __forceinline__ void smx_fence_async() {
    asm volatile("fence.proxy.async.shared::cta;" ::: "memory");
}

extern __shared__ float smx_buf[];   // 32000 floats = 128 KB

__global__ __launch_bounds__(SMX_THREADS, 1)
void sparsemax_kernel(const float* __restrict__ x, float* __restrict__ y, int rows) {
    const int t    = threadIdx.x;
    const int lane = t & 31;
    const int warp = t >> 5;
    const int stride = gridDim.x;

    __shared__ __align__(8) uint64_t s_mbar;
    __shared__ __align__(16) float s_warpmax[32];
    __shared__ int      s_cnt[2];
    __shared__ float    s_red[2][2];          // fallback accumulators
    __shared__ float    s_cand[2][SMX_CAP];

    const uint32_t mbar = smx_smem_u32(&s_mbar);
    const uint32_t sbuf = smx_smem_u32(smx_buf);

    if (t == 0) {
        smx_mbar_init(mbar, 1);
        s_cnt[0] = 0;  s_cnt[1] = 0;
    }
    __syncthreads();

    const int row0 = blockIdx.x;
    if (row0 >= rows) return;

    if (t == 0) {
        smx_expect_tx(mbar, SMX_ROWBYTES);
        smx_bulk_g2s(sbuf, x + (size_t)row0 * SMX_N, SMX_ROWBYTES, mbar);
    }

    uint32_t parity = 0;   // mbarrier phase
    unsigned p = 0;        // row-parity for candidate scratch slots

    for (int r = row0; r < rows; r += stride) {
        smx_mbar_wait(mbar, parity);
        parity ^= 1u;

        // ---- SMEM -> registers with fused running max ----
        float4 v[8];
        float m = SMX_NEG;
        const float4* s4 = reinterpret_cast<const float4*>(smx_buf);
        #pragma unroll
        for (int i = 0; i < 7; i++) {
            v[i] = s4[i * SMX_THREADS + t];
            m = fmaxf(m, fmaxf(fmaxf(v[i].x, v[i].y), fmaxf(v[i].z, v[i].w)));
        }
        if (t < SMX_LAST_F4) {
            v[7] = s4[7 * SMX_THREADS + t];
            m = fmaxf(m, fmaxf(fmaxf(v[7].x, v[7].y), fmaxf(v[7].z, v[7].w)));
        } else {
            v[7] = make_float4(SMX_NEG, SMX_NEG, SMX_NEG, SMX_NEG);
        }

        // warp max-reduce, publish via plain STS (no atomic serialization
        // on the pre-barrier critical path)
        #pragma unroll
        for (int o = 16; o; o >>= 1)
            m = fmaxf(m, __shfl_xor_sync(0xffffffffu, m, o));
        if (lane == 0) s_warpmax[warp] = m;

        __syncthreads();   // barrier A: buffer reads done + warp maxima published

        // t0: release buffer to the async proxy, prefetch next row (earliest
        // possible point — this is the DRAM-critical instruction of the loop)
        if (t == 0 && r + stride < rows) {
            smx_fence_async();
            smx_expect_tx(mbar, SMX_ROWBYTES);
            smx_bulk_g2s(sbuf, x + (size_t)(r + stride) * SMX_N, SMX_ROWBYTES, mbar);
        }

        // every thread combines the 32 warp maxima (off the TMA-issue path)
        float rowmax;
        {
            const float4* w4 = reinterpret_cast<const float4*>(s_warpmax);
            float4 a = w4[0], b = w4[1], c = w4[2], d = w4[3];
            float4 e = w4[4], f = w4[5], g = w4[6], h = w4[7];
            float m0 = fmaxf(fmaxf(fmaxf(a.x, a.y), fmaxf(a.z, a.w)),
                             fmaxf(fmaxf(b.x, b.y), fmaxf(b.z, b.w)));
            float m1 = fmaxf(fmaxf(fmaxf(c.x, c.y), fmaxf(c.z, c.w)),
                             fmaxf(fmaxf(d.x, d.y), fmaxf(d.z, d.w)));
            float m2 = fmaxf(fmaxf(fmaxf(e.x, e.y), fmaxf(e.z, e.w)),
                             fmaxf(fmaxf(f.x, f.y), fmaxf(f.z, f.w)));
            float m3 = fmaxf(fmaxf(fmaxf(g.x, g.y), fmaxf(g.z, g.w)),
                             fmaxf(fmaxf(h.x, h.y), fmaxf(h.z, h.w)));
            rowmax = fmaxf(fmaxf(m0, m1), fmaxf(m2, m3));
        }
        const float thr = rowmax - 1.0f;       // tau >= thr always

        // ---- compact candidates {x > thr} into s_cand[p] ----
        int*   cntp  = &s_cnt[p];
        float* candp = s_cand[p];
        if (t == 1) s_cnt[p ^ 1] = 0;          // prep next row's slot
        #pragma unroll
        for (int i = 0; i < 8; i++) {
            const float a0 = v[i].x, a1 = v[i].y, a2 = v[i].z, a3 = v[i].w;
            if (a0 > thr) { int k = atomicAdd(cntp, 1); if (k < SMX_CAP) candp[k] = a0; }
            if (a1 > thr) { int k = atomicAdd(cntp, 1); if (k < SMX_CAP) candp[k] = a1; }
            if (a2 > thr) { int k = atomicAdd(cntp, 1); if (k < SMX_CAP) candp[k] = a2; }
            if (a3 > thr) { int k = atomicAdd(cntp, 1); if (k < SMX_CAP) candp[k] = a3; }
        }
        __syncthreads();   // barrier B: candidate list complete
        const int cnt = *cntp;

        float tau;
        if (cnt <= SMX_CAP) {
            // ---- every warp redundantly: Michelot on the candidate list ----
            tau = thr;
            float prevc = -1.0f;
            #pragma unroll 1
            for (int it = 0; it < 64; it++) {
                float s = 0.0f, c = 0.0f;
                for (int j = lane; j < cnt; j += 32) {
                    const float z = candp[j];
                    if (z > tau) { s += z; c += 1.0f; }
                }
                #pragma unroll
                for (int o = 16; o; o >>= 1) {
                    s += __shfl_xor_sync(0xffffffffu, s, o);
                    c += __shfl_xor_sync(0xffffffffu, c, o);
                }
                tau = (s - 1.0f) / c;
                if (c == prevc) break;        // fixed point: exact tau
                prevc = c;
            }
        } else {
            // ---- fallback: full-row Michelot via shared atomics (rare) ----
            if (t == 0) { s_red[0][0] = 0.f; s_red[0][1] = 0.f;
                          s_red[1][0] = 0.f; s_red[1][1] = 0.f; }
            __syncthreads();
            tau = thr;
            float prevc = -1.0f;
            unsigned q = 0;
            #pragma unroll 1
            for (int it = 0; it < 64; it++) {
                float s = 0.0f, c = 0.0f;
                #pragma unroll
                for (int i = 0; i < 8; i++) {
                    if (v[i].x > tau) { s += v[i].x; c += 1.0f; }
                    if (v[i].y > tau) { s += v[i].y; c += 1.0f; }
                    if (v[i].z > tau) { s += v[i].z; c += 1.0f; }
                    if (v[i].w > tau) { s += v[i].w; c += 1.0f; }
                }
                #pragma unroll
                for (int o = 16; o; o >>= 1) {
                    s += __shfl_xor_sync(0xffffffffu, s, o);
                    c += __shfl_xor_sync(0xffffffffu, c, o);
                }
                if (lane == 0) { atomicAdd(&s_red[q][0], s); atomicAdd(&s_red[q][1], c); }
                if (t == 0)    { s_red[q ^ 1][0] = 0.f; s_red[q ^ 1][1] = 0.f; }
                __syncthreads();
                const float S = s_red[q][0], C = s_red[q][1];
                __syncthreads();
                tau = (S - 1.0f) / C;
                if (C == prevc) break;
                prevc = C;
                q ^= 1;
            }
        }

        // ---- output: max(x - tau, 0), coalesced, evict-first ----
        float4* __restrict__ yr = reinterpret_cast<float4*>(y + (size_t)r * SMX_N);
        #pragma unroll
        for (int i = 0; i < 7; i++) {
            float4 o;
            o.x = fmaxf(v[i].x - tau, 0.0f);
            o.y = fmaxf(v[i].y - tau, 0.0f);
            o.z = fmaxf(v[i].z - tau, 0.0f);
            o.w = fmaxf(v[i].w - tau, 0.0f);
            __stcs(&yr[i * SMX_THREADS + t], o);
        }
        if (t < SMX_LAST_F4) {
            float4 o;
            o.x = fmaxf(v[7].x - tau, 0.0f);
            o.y = fmaxf(v[7].y - tau, 0.0f);
            o.z = fmaxf(v[7].z - tau, 0.0f);
            o.w = fmaxf(v[7].w - tau, 0.0f);
            __stcs(&yr[7 * SMX_THREADS + t], o);
        }

        p ^= 1u;
    }
}

extern "C" void kernel_launch(void* const* d_in, const int* in_sizes, int n_in,
                              void* d_out, int out_size) {
    const float* x = (const float*)d_in[0];
    float* y = (float*)d_out;
    const int rows = in_sizes[0] / SMX_N;

    int dev = 0, sms = 148;
    cudaGetDevice(&dev);
    cudaDeviceGetAttribute(&sms, cudaDevAttrMultiProcessorCount, dev);

    static bool attr_done = false;
    if (!attr_done) {
        cudaFuncSetAttribute(sparsemax_kernel,
                             cudaFuncAttributeMaxDynamicSharedMemorySize,
                             SMX_ROWBYTES);
        attr_done = true;
    }

    int grid = rows < sms ? rows : sms;
    sparsemax_kernel<<<grid, SMX_THREADS, SMX_ROWBYTES>>>(x, y, rows);
}